// round 7
// baseline (speedup 1.0000x reference)
#include <cuda_runtime.h>
#include <cuda_bf16.h>

// GruDirection3d forward wavefront:
//   out[d,y,x] = z*h_tilde + (1-z)*out[d-1,y-1,x-1],  border -> h0
//
// Plane sweep, one CTA (1024 thr) per (b,c) volume, BUT two planes per
// barrier: thread (y,x) computes out[p0][y][x] from the smem ext tile, then
// out[p1][y+1][x+1] from that value IN REGISTER (diagonal dependency).
// Threads with y==31 / x==31 instead compute plane p1's row-0/col-0 border
// cells (prev = h0). The remap is a rotation within each row, so every gmem
// and smem access stays one-line coalesced. 16 barriers instead of 32.

#define PLANE 1024     // 32*32
#define EXT 33

__global__ __launch_bounds__(1024, 1)
void gru3d_kernel(const float* __restrict__ z,
                  const float* __restrict__ ht,
                  const float* __restrict__ h0p,
                  float* __restrict__ out)
{
    __shared__ float buf[2][EXT * EXT];

    const float h0 = __ldg(h0p);
    const int tid = threadIdx.x;

    // Init both buffers to h0; row 0 / col 0 are never overwritten.
    #pragma unroll
    for (int i = tid; i < 2 * EXT * EXT; i += 1024)
        (&buf[0][0])[i] = h0;

    const int y = tid >> 5;
    const int x = tid & 31;

    const int idx0 = y * 32 + x;             // plane-p0 position
    // plane-p1 position (diagonal successor, borders remapped):
    //   y==31        -> (0, x)        border row 0
    //   x==31 (y<31) -> (y+1, 0)      border col 0
    //   else         -> (y+1, x+1)    interior
    const bool edge = (y == 31) | (x == 31);
    int idx1, w1;
    if (y == 31)      { idx1 = x;                w1 = 1 * EXT + (x + 1); }
    else if (x == 31) { idx1 = (y + 1) * 32;     w1 = (y + 2) * EXT + 1; }
    else              { idx1 = idx0 + 33;        w1 = (y + 2) * EXT + (x + 2); }

    const int ridx = y * EXT + x;            // ext coords of prev (y-1,x-1)

    const size_t vbase = (size_t)blockIdx.x * (32 * PLANE);
    const float* zp0 = z  + vbase + idx0;
    const float* hp0 = ht + vbase + idx0;
    const float* zp1 = z  + vbase + idx1;
    const float* hp1 = ht + vbase + idx1;
    float*       op  = out + vbase;

    // Two-group (4-plane) prefetch pipeline.
    float zA[2], hA[2], zB[2], hB[2];
    #pragma unroll
    for (int s = 0; s < 2; ++s) {
        zA[s] = zp0[(size_t)(2 * s)     * PLANE];
        hA[s] = hp0[(size_t)(2 * s)     * PLANE];
        zB[s] = zp1[(size_t)(2 * s + 1) * PLANE];
        hB[s] = hp1[(size_t)(2 * s + 1) * PLANE];
    }

    __syncthreads();   // buffer init visible

    #pragma unroll
    for (int g = 0; g < 16; ++g) {
        const int s = g & 1;
        const float z0 = zA[s], hh0 = hA[s];
        const float z1 = zB[s], hh1 = hB[s];

        // Refill this stage with group g+2.
        if (g + 2 < 16) {
            zA[s] = zp0[(size_t)(2 * g + 4) * PLANE];
            hA[s] = hp0[(size_t)(2 * g + 4) * PLANE];
            zB[s] = zp1[(size_t)(2 * g + 5) * PLANE];
            hB[s] = hp1[(size_t)(2 * g + 5) * PLANE];
        }

        // Plane p0 = 2g: prev from smem ext tile (h0 on borders).
        const float p = buf[(g + 1) & 1][ridx];
        const float o0 = fmaf(z0, hh0 - p, p);
        op[(size_t)(2 * g) * PLANE + idx0] = o0;

        // Plane p1 = 2g+1: interior prev = o0 (in register); borders = h0.
        const float pb = edge ? h0 : o0;
        const float o1 = fmaf(z1, hh1 - pb, pb);
        buf[g & 1][w1] = o1;
        op[(size_t)(2 * g + 1) * PLANE + idx1] = o1;

        __syncthreads();   // o1 writes visible before group g+1 reads
    }
}

extern "C" void kernel_launch(void* const* d_in, const int* in_sizes, int n_in,
                              void* d_out, int out_size)
{
    const float* z  = (const float*)d_in[0];
    const float* ht = (const float*)d_in[1];
    const float* h0 = (const float*)d_in[2];
    float* out = (float*)d_out;

    const int n_volumes = out_size / (32 * PLANE);   // B*C = 192
    gru3d_kernel<<<n_volumes, 1024>>>(z, ht, h0, out);
}